// round 2
// baseline (speedup 1.0000x reference)
#include <cuda_runtime.h>
#include <cstdint>
#include <math.h>

// Problem constants (fixed by the dataset):
// B=512, C=3, N=128, k=3, L=3
#define CC 3
#define NN 128
#define NPIX (NN*NN)          // 16384
#define CPIX (CC*NPIX)        // 49152
#define LL 3

__device__ float g_const_logdet;

// ---------------------------------------------------------------------------
// Prologue: data-independent part of total_logdet
//   per layer l:  n^2 * sum(actnorm_log_scale[l])
//               + sum(conv_log_scale[l])
//               + sum_{u,v} log|det( FFT2(pad(K[l]))[.,.,u,v] )|
// grid = 3 blocks (one per layer), 256 threads.
// ---------------------------------------------------------------------------
__global__ void flow_const_kernel(const float* __restrict__ anls,
                                  const float* __restrict__ Kall,
                                  const float* __restrict__ cls)
{
    const int layer = blockIdx.x;
    const int tid   = threadIdx.x;
    __shared__ float red[256];

    // kernel weights for this layer into registers
    float kreg[81];
    const float* Kl = Kall + layer * 81;
#pragma unroll
    for (int i = 0; i < 81; i++) kreg[i] = Kl[i];

    float acc = 0.f;

    // spectral log|det| over 128x128 frequencies
    for (int f = tid; f < NPIX; f += 256) {
        const int u = f >> 7;
        const int v = f & 127;
        float mre[3][3], mim[3][3];
#pragma unroll
        for (int o = 0; o < 3; o++)
#pragma unroll
            for (int i2 = 0; i2 < 3; i2++) { mre[o][i2] = 0.f; mim[o][i2] = 0.f; }

#pragma unroll
        for (int a = 0; a < 3; a++) {
#pragma unroll
            for (int b2 = 0; b2 < 3; b2++) {
                const int m = (u * a + v * b2) & 127;     // phase mod n
                float sp, cp;
                sincospif((float)m * (1.0f / 64.0f), &sp, &cp);  // angle = 2*pi*m/128
                // w = exp(-i*angle) = cp - i*sp
#pragma unroll
                for (int o = 0; o < 3; o++)
#pragma unroll
                    for (int i2 = 0; i2 < 3; i2++) {
                        const float kw = kreg[((o * 3 + i2) * 3 + a) * 3 + b2];
                        mre[o][i2] = fmaf(kw, cp, mre[o][i2]);
                        mim[o][i2] = fmaf(-kw, sp, mim[o][i2]);
                    }
            }
        }
        // complex 3x3 determinant
        // minors
        float c0r = mre[1][1] * mre[2][2] - mim[1][1] * mim[2][2]
                  - (mre[1][2] * mre[2][1] - mim[1][2] * mim[2][1]);
        float c0i = mre[1][1] * mim[2][2] + mim[1][1] * mre[2][2]
                  - (mre[1][2] * mim[2][1] + mim[1][2] * mre[2][1]);
        float c1r = mre[1][0] * mre[2][2] - mim[1][0] * mim[2][2]
                  - (mre[1][2] * mre[2][0] - mim[1][2] * mim[2][0]);
        float c1i = mre[1][0] * mim[2][2] + mim[1][0] * mre[2][2]
                  - (mre[1][2] * mim[2][0] + mim[1][2] * mre[2][0]);
        float c2r = mre[1][0] * mre[2][1] - mim[1][0] * mim[2][1]
                  - (mre[1][1] * mre[2][0] - mim[1][1] * mim[2][0]);
        float c2i = mre[1][0] * mim[2][1] + mim[1][0] * mre[2][1]
                  - (mre[1][1] * mim[2][0] + mim[1][1] * mre[2][0]);
        // det = A*c0 - B*c1 + C*c2   (A=m00, B=m01, C=m02), complex
        float dr = (mre[0][0] * c0r - mim[0][0] * c0i)
                 - (mre[0][1] * c1r - mim[0][1] * c1i)
                 + (mre[0][2] * c2r - mim[0][2] * c2i);
        float di = (mre[0][0] * c0i + mim[0][0] * c0r)
                 - (mre[0][1] * c1i + mim[0][1] * c1r)
                 + (mre[0][2] * c2i + mim[0][2] * c2r);
        acc += 0.5f * logf(dr * dr + di * di);
    }

    // + sum(conv_log_scale[layer])
    const float* cl = cls + layer * CPIX;
    for (int i = tid; i < CPIX; i += 256) acc += cl[i];

    // + n^2 * sum(actnorm_log_scale[layer])
    if (tid == 0) {
        float s = anls[layer * 3 + 0] + anls[layer * 3 + 1] + anls[layer * 3 + 2];
        acc += (float)NPIX * s;
    }

    red[tid] = acc;
    __syncthreads();
#pragma unroll
    for (int s2 = 128; s2 > 0; s2 >>= 1) {
        if (tid < s2) red[tid] += red[tid + s2];
        __syncthreads();
    }
    if (tid == 0) atomicAdd(&g_const_logdet, red[0]);
}

// ---------------------------------------------------------------------------
// Main fused kernel: 1 CTA per batch image, entire image resident in SMEM.
// All 3 layers fused: actnorm folded into conv weights; in-place update via
// 8 row-chunks with halo backup rows; last layer writes directly to GMEM.
// ---------------------------------------------------------------------------
#define THREADS 512
#define SMEM_FLOATS (CPIX + 384 + 384 + THREADS)   // img + bakPrev + bak0 + red
#define SMEM_BYTES  (SMEM_FLOATS * 4)

__global__ __launch_bounds__(THREADS, 1)
void flow_main_kernel(const float* __restrict__ x,
                      const float* __restrict__ anb,
                      const float* __restrict__ anls,
                      const float* __restrict__ Kall,
                      const float* __restrict__ cbias,
                      const float* __restrict__ cls,
                      const float* __restrict__ slal,
                      float* __restrict__ out_h,
                      float* __restrict__ out_ld)
{
    extern __shared__ float sm[];
    float* img  = sm;                 // [3][128][128]
    float* bakP = sm + CPIX;          // [3][128] previous boundary row (pre-image)
    float* bak0 = sm + CPIX + 384;    // [3][128] row 0 pre-image (per layer)
    float* red  = sm + CPIX + 768;    // [512]

    const int b   = blockIdx.x;
    const int tid = threadIdx.x;
    const int w   = tid >> 5;
    const int l   = tid & 31;

    // load image
    {
        const float4* x4 = (const float4*)(x + (size_t)b * CPIX);
        float4* s4 = (float4*)img;
        for (int i = tid; i < CPIX / 4; i += THREADS) s4[i] = x4[i];
    }
    __syncthreads();

    float ldacc = 0.f;

#pragma unroll 1
    for (int layer = 0; layer < LL; ++layer) {
        // ---- fold actnorm into conv weights (all threads redundantly) ----
        float W[3][3][3][3];
        float cadd[3], alpha[3], inva[3];
        {
            const float* Kl = Kall + layer * 81;
            float s[3], bb[3];
#pragma unroll
            for (int i = 0; i < 3; i++) {
                s[i]  = __expf(anls[layer * 3 + i]);
                bb[i] = anb[layer * 3 + i];
                alpha[i] = __expf(slal[layer * 3 + i]);
                inva[i]  = 1.0f / alpha[i];
            }
#pragma unroll
            for (int o = 0; o < 3; o++) {
                float ca = 0.f;
#pragma unroll
                for (int i = 0; i < 3; i++) {
                    float ks = 0.f;
#pragma unroll
                    for (int a = 0; a < 3; a++)
#pragma unroll
                        for (int d = 0; d < 3; d++) {
                            const float kw = Kl[((o * 3 + i) * 3 + a) * 3 + d];
                            W[o][i][a][d] = kw * s[i];
                            ks += kw;
                        }
                    ca = fmaf(ks, bb[i], ca);
                }
                cadd[o] = ca;
            }
        }
        const float* clsl = cls   + layer * CPIX;
        const float* cbl  = cbias + layer * CPIX;

        if (layer < LL - 1) {
            // ---- in-place layer: 8 chunks of 16 rows ----
#pragma unroll 1
            for (int k = 0; k < 8; k++) {
                const int k16 = k << 4;
                float res[4][3];
#pragma unroll
                for (int j = 0; j < 4; j++) {
                    const int p  = ((j * 16 + w) << 5) + l;
                    const int ry = p >> 7;
                    const int xx = p & 127;
                    const int y  = k16 + ry;

                    const float* rb[3];
                    int cs[3];
#pragma unroll
                    for (int a = 0; a < 3; a++) {
                        const int yy = y + a - 1;
                        if (yy < k16) {
                            if (k == 0) { rb[a] = img + 127 * 128; cs[a] = NPIX; }
                            else        { rb[a] = bakP;            cs[a] = 128; }
                        } else if (yy >= k16 + 16) {
                            if (k == 7) { rb[a] = bak0;            cs[a] = 128; }
                            else        { rb[a] = img + yy * 128;  cs[a] = NPIX; }
                        } else          { rb[a] = img + yy * 128;  cs[a] = NPIX; }
                    }
                    int xm[3];
                    xm[0] = (xx + 127) & 127; xm[1] = xx; xm[2] = (xx + 1) & 127;

                    float a0 = cadd[0], a1 = cadd[1], a2 = cadd[2];
#pragma unroll
                    for (int i = 0; i < 3; i++)
#pragma unroll
                        for (int a = 0; a < 3; a++) {
                            const float* r = rb[a] + i * cs[a];
#pragma unroll
                            for (int d = 0; d < 3; d++) {
                                const float v = r[xm[d]];
                                a0 = fmaf(W[0][i][a][d], v, a0);
                                a1 = fmaf(W[1][i][a][d], v, a1);
                                a2 = fmaf(W[2][i][a][d], v, a2);
                            }
                        }
                    float accv[3] = {a0, a1, a2};
#pragma unroll
                    for (int o = 0; o < 3; o++) {
                        const int gi = o * NPIX + y * 128 + xx;
                        const float e = __expf(clsl[gi]);
                        const float v = fmaf(e, accv[o], cbl[gi]);
                        const float t = __logf(fmaf(alpha[o], fabsf(v), 1.0f));
                        ldacc -= t;
                        res[j][o] = copysignf(t * inva[o], v);
                    }
                }
                __syncthreads();
                // save halo rows (pre-image) then write outputs; per-thread
                // save-before-write ordering makes this race-free.
#pragma unroll
                for (int j = 0; j < 4; j++) {
                    const int p  = ((j * 16 + w) << 5) + l;
                    const int ry = p >> 7;
                    const int xx = p & 127;
                    const int y  = k16 + ry;
                    if (ry == 15) {
#pragma unroll
                        for (int c2 = 0; c2 < 3; c2++)
                            bakP[c2 * 128 + xx] = img[c2 * NPIX + y * 128 + xx];
                    }
                    if (k == 0 && ry == 0) {
#pragma unroll
                        for (int c2 = 0; c2 < 3; c2++)
                            bak0[c2 * 128 + xx] = img[c2 * NPIX + y * 128 + xx];
                    }
#pragma unroll
                    for (int o = 0; o < 3; o++)
                        img[o * NPIX + y * 128 + xx] = res[j][o];
                }
                __syncthreads();
            }
        } else {
            // ---- last layer: read SMEM, write straight to GMEM ----
            float* ob = out_h + (size_t)b * CPIX;
#pragma unroll 1
            for (int it = 0; it < 32; ++it) {
                const int p  = ((it * 16 + w) << 5) + l;
                const int y  = p >> 7;
                const int xx = p & 127;
                int ym[3], xm[3];
                ym[0] = (y + 127) & 127; ym[1] = y; ym[2] = (y + 1) & 127;
                xm[0] = (xx + 127) & 127; xm[1] = xx; xm[2] = (xx + 1) & 127;

                float a0 = cadd[0], a1 = cadd[1], a2 = cadd[2];
#pragma unroll
                for (int i = 0; i < 3; i++)
#pragma unroll
                    for (int a = 0; a < 3; a++) {
                        const float* r = img + i * NPIX + ym[a] * 128;
#pragma unroll
                        for (int d = 0; d < 3; d++) {
                            const float v = r[xm[d]];
                            a0 = fmaf(W[0][i][a][d], v, a0);
                            a1 = fmaf(W[1][i][a][d], v, a1);
                            a2 = fmaf(W[2][i][a][d], v, a2);
                        }
                    }
                float accv[3] = {a0, a1, a2};
#pragma unroll
                for (int o = 0; o < 3; o++) {
                    const int gi = o * NPIX + y * 128 + xx;
                    const float e = __expf(clsl[gi]);
                    const float v = fmaf(e, accv[o], cbl[gi]);
                    const float t = __logf(fmaf(alpha[o], fabsf(v), 1.0f));
                    ldacc -= t;
                    ob[gi] = copysignf(t * inva[o], v);
                }
            }
        }
    }

    // ---- per-batch logdet reduction ----
    red[tid] = ldacc;
    __syncthreads();
#pragma unroll
    for (int s2 = 256; s2 > 0; s2 >>= 1) {
        if (tid < s2) red[tid] += red[tid + s2];
        __syncthreads();
    }
    if (tid == 0) out_ld[b] = red[0] + g_const_logdet;
}

// ---------------------------------------------------------------------------
extern "C" void kernel_launch(void* const* d_in, const int* in_sizes, int n_in,
                              void* d_out, int out_size)
{
    const float* x    = (const float*)d_in[0];
    const float* anb  = (const float*)d_in[1];
    const float* anls = (const float*)d_in[2];
    const float* K    = (const float*)d_in[3];
    const float* cb   = (const float*)d_in[4];
    const float* cls  = (const float*)d_in[5];
    const float* slal = (const float*)d_in[6];

    const int B = in_sizes[0] / CPIX;           // 512
    float* out_h  = (float*)d_out;
    float* out_ld = (float*)d_out + (out_size - B);

    void* sym = nullptr;
    cudaGetSymbolAddress(&sym, g_const_logdet);
    cudaMemsetAsync(sym, 0, sizeof(float));

    flow_const_kernel<<<LL, 256>>>(anls, K, cls);

    static int smem_set = 0;
    if (!smem_set) {
        cudaFuncSetAttribute(flow_main_kernel,
                             cudaFuncAttributeMaxDynamicSharedMemorySize,
                             SMEM_BYTES);
        smem_set = 1;
    }
    flow_main_kernel<<<B, THREADS, SMEM_BYTES>>>(x, anb, anls, K, cb, cls, slal,
                                                 out_h, out_ld);
}

// round 3
// speedup vs baseline: 1.3552x; 1.3552x over previous
#include <cuda_runtime.h>
#include <cstdint>
#include <math.h>

// Problem constants (fixed by the dataset):
// B=512, C=3, N=128, k=3, L=3
#define CC 3
#define NN 128
#define NPIX (NN*NN)          // 16384
#define CPIX (CC*NPIX)        // 49152
#define LL 3

#define CONST_BLOCKS (LL * 16)      // 48
__device__ float g_partial[CONST_BLOCKS];

// ---------------------------------------------------------------------------
// Prologue: data-independent part of total_logdet.
// grid = 48 blocks (3 layers x 16 freq-chunks), 256 threads.
// Each block writes its partial sum to g_partial[bid]; main kernel sums them.
// ---------------------------------------------------------------------------
__global__ void flow_const_kernel(const float* __restrict__ anls,
                                  const float* __restrict__ Kall,
                                  const float* __restrict__ cls)
{
    const int layer = blockIdx.x >> 4;
    const int chunk = blockIdx.x & 15;
    const int tid   = threadIdx.x;
    __shared__ float red[256];

    float kreg[81];
    const float* Kl = Kall + layer * 81;
#pragma unroll
    for (int i = 0; i < 81; i++) kreg[i] = Kl[i];

    float acc = 0.f;

    // spectral log|det| over this chunk's 1024 frequencies
    for (int ff = tid; ff < 1024; ff += 256) {
        const int f = chunk * 1024 + ff;
        const int u = f >> 7;
        const int v = f & 127;
        float mre[3][3], mim[3][3];
#pragma unroll
        for (int o = 0; o < 3; o++)
#pragma unroll
            for (int i2 = 0; i2 < 3; i2++) { mre[o][i2] = 0.f; mim[o][i2] = 0.f; }

#pragma unroll
        for (int a = 0; a < 3; a++) {
#pragma unroll
            for (int b2 = 0; b2 < 3; b2++) {
                const int m = (u * a + v * b2) & 127;
                float sp, cp;
                sincospif((float)m * (1.0f / 64.0f), &sp, &cp);
#pragma unroll
                for (int o = 0; o < 3; o++)
#pragma unroll
                    for (int i2 = 0; i2 < 3; i2++) {
                        const float kw = kreg[((o * 3 + i2) * 3 + a) * 3 + b2];
                        mre[o][i2] = fmaf(kw, cp, mre[o][i2]);
                        mim[o][i2] = fmaf(-kw, sp, mim[o][i2]);
                    }
            }
        }
        float c0r = mre[1][1] * mre[2][2] - mim[1][1] * mim[2][2]
                  - (mre[1][2] * mre[2][1] - mim[1][2] * mim[2][1]);
        float c0i = mre[1][1] * mim[2][2] + mim[1][1] * mre[2][2]
                  - (mre[1][2] * mim[2][1] + mim[1][2] * mre[2][1]);
        float c1r = mre[1][0] * mre[2][2] - mim[1][0] * mim[2][2]
                  - (mre[1][2] * mre[2][0] - mim[1][2] * mim[2][0]);
        float c1i = mre[1][0] * mim[2][2] + mim[1][0] * mre[2][2]
                  - (mre[1][2] * mim[2][0] + mim[1][2] * mre[2][0]);
        float c2r = mre[1][0] * mre[2][1] - mim[1][0] * mim[2][1]
                  - (mre[1][1] * mre[2][0] - mim[1][1] * mim[2][0]);
        float c2i = mre[1][0] * mim[2][1] + mim[1][0] * mre[2][1]
                  - (mre[1][1] * mim[2][0] + mim[1][1] * mre[2][0]);
        float dr = (mre[0][0] * c0r - mim[0][0] * c0i)
                 - (mre[0][1] * c1r - mim[0][1] * c1i)
                 + (mre[0][2] * c2r - mim[0][2] * c2i);
        float di = (mre[0][0] * c0i + mim[0][0] * c0r)
                 - (mre[0][1] * c1i + mim[0][1] * c1r)
                 + (mre[0][2] * c2i + mim[0][2] * c2r);
        acc += 0.5f * logf(dr * dr + di * di);
    }

    // distributed sum(conv_log_scale[layer]) : this chunk's 3072 elements
    const float* cl = cls + layer * CPIX + chunk * (CPIX / 16);
    for (int i = tid; i < CPIX / 16; i += 256) acc += cl[i];

    if (chunk == 0 && tid == 0) {
        float s = anls[layer * 3 + 0] + anls[layer * 3 + 1] + anls[layer * 3 + 2];
        acc += (float)NPIX * s;
    }

    red[tid] = acc;
    __syncthreads();
#pragma unroll
    for (int s2 = 128; s2 > 0; s2 >>= 1) {
        if (tid < s2) red[tid] += red[tid + s2];
        __syncthreads();
    }
    if (tid == 0) g_partial[blockIdx.x] = red[0];
}

// ---------------------------------------------------------------------------
// Main fused kernel: 1 CTA per image, whole image in SMEM, 3 layers fused.
// 16 warps; each warp processes one full row per step; each lane owns 4
// consecutive pixels (float4 LDS + shfl halos => x-wrap free).
// ---------------------------------------------------------------------------
#define THREADS 512
#define SMEM_FLOATS (CPIX + 384 + 384 + THREADS)   // img + bakP + bak0 + red
#define SMEM_BYTES  (SMEM_FLOATS * 4)

__global__ __launch_bounds__(THREADS, 1)
void flow_main_kernel(const float* __restrict__ x,
                      const float* __restrict__ anb,
                      const float* __restrict__ anls,
                      const float* __restrict__ Kall,
                      const float* __restrict__ cbias,
                      const float* __restrict__ cls,
                      const float* __restrict__ slal,
                      float* __restrict__ out_h,
                      float* __restrict__ out_ld)
{
    extern __shared__ float sm[];
    float* img  = sm;                 // [3][128][128]
    float* bakP = sm + CPIX;          // [3][128] pre-image of chunk boundary row
    float* bak0 = sm + CPIX + 384;    // [3][128] pre-image of row 0
    float* red  = sm + CPIX + 768;    // [512]

    const int b   = blockIdx.x;
    const int tid = threadIdx.x;
    const int w   = tid >> 5;         // warp id (= row within chunk)
    const int l   = tid & 31;
    const int x0  = l << 2;           // lane's 4-pixel base
    const int lm1 = (l + 31) & 31;
    const int lp1 = (l + 1) & 31;

    // load image (float4 coalesced)
    {
        const float4* x4 = (const float4*)(x + (size_t)b * CPIX);
        float4* s4 = (float4*)img;
        for (int i = tid; i < CPIX / 4; i += THREADS) s4[i] = x4[i];
    }
    __syncthreads();

    float ldacc = 0.f;

#pragma unroll 1
    for (int layer = 0; layer < LL; ++layer) {
        // ---- fold actnorm into conv weights (all threads redundantly) ----
        float W[3][3][3][3];
        float cadd[3], alpha[3], inva[3];
        {
            const float* Kl = Kall + layer * 81;
            float s[3], bb[3];
#pragma unroll
            for (int i = 0; i < 3; i++) {
                s[i]  = __expf(anls[layer * 3 + i]);
                bb[i] = anb[layer * 3 + i];
                alpha[i] = __expf(slal[layer * 3 + i]);
                inva[i]  = 1.0f / alpha[i];
            }
#pragma unroll
            for (int o = 0; o < 3; o++) {
                float ca = 0.f;
#pragma unroll
                for (int i = 0; i < 3; i++) {
                    float ks = 0.f;
#pragma unroll
                    for (int a = 0; a < 3; a++)
#pragma unroll
                        for (int d = 0; d < 3; d++) {
                            const float kw = Kl[((o * 3 + i) * 3 + a) * 3 + d];
                            W[o][i][a][d] = kw * s[i];
                            ks += kw;
                        }
                    ca = fmaf(ks, bb[i], ca);
                }
                cadd[o] = ca;
            }
        }
        const float* clsl = cls   + layer * CPIX;
        const float* cbl  = cbias + layer * CPIX;

        if (layer < LL - 1) {
            // ---- in-place layer: 8 chunks of 16 rows (1 row per warp) ----
#pragma unroll 1
            for (int k = 0; k < 8; k++) {
                const int y = (k << 4) + w;

                // row base pointers (channel-0) + channel strides
                const float* rp[3];
                int cs[3];
                if (w == 0) {
                    if (k == 0) { rp[0] = img + 127 * 128; cs[0] = NPIX; }
                    else        { rp[0] = bakP;            cs[0] = 128; }
                } else          { rp[0] = img + (y - 1) * 128; cs[0] = NPIX; }
                rp[1] = img + y * 128; cs[1] = NPIX;
                if (w == 15 && k == 7) { rp[2] = bak0; cs[2] = 128; }
                else                   { rp[2] = img + (y + 1) * 128; cs[2] = NPIX; }

                float acc[3][4];
#pragma unroll
                for (int o = 0; o < 3; o++)
#pragma unroll
                    for (int p = 0; p < 4; p++) acc[o][p] = cadd[o];

#pragma unroll
                for (int i = 0; i < 3; i++)
#pragma unroll
                    for (int a = 0; a < 3; a++) {
                        const float* r = rp[a] + i * cs[a];
                        const float4 vm = *(const float4*)(r + x0);
                        const float v0 = __shfl_sync(0xffffffffu, vm.w, lm1);
                        const float v5 = __shfl_sync(0xffffffffu, vm.x, lp1);
                        const float v[6] = {v0, vm.x, vm.y, vm.z, vm.w, v5};
#pragma unroll
                        for (int o = 0; o < 3; o++)
#pragma unroll
                            for (int p = 0; p < 4; p++)
#pragma unroll
                                for (int d = 0; d < 3; d++)
                                    acc[o][p] = fmaf(W[o][i][a][d], v[p + d], acc[o][p]);
                    }

                // epilogue: per-pixel scale/bias + slog gate
                float res[3][4];
#pragma unroll
                for (int o = 0; o < 3; o++) {
                    const int gi = o * NPIX + y * 128 + x0;
                    const float4 c4 = *(const float4*)(clsl + gi);
                    const float4 b4 = *(const float4*)(cbl + gi);
                    const float cp[4] = {c4.x, c4.y, c4.z, c4.w};
                    const float bp[4] = {b4.x, b4.y, b4.z, b4.w};
#pragma unroll
                    for (int p = 0; p < 4; p++) {
                        const float e = __expf(cp[p]);
                        const float v = fmaf(e, acc[o][p], bp[p]);
                        const float t = __logf(fmaf(alpha[o], fabsf(v), 1.0f));
                        ldacc -= t;
                        res[o][p] = copysignf(t * inva[o], v);
                    }
                }
                __syncthreads();
                // save halo rows (pre-image), then overwrite (same-thread order)
                if (w == 15) {
#pragma unroll
                    for (int c2 = 0; c2 < 3; c2++)
                        *(float4*)(bakP + c2 * 128 + x0) =
                            *(const float4*)(img + c2 * NPIX + y * 128 + x0);
                }
                if (k == 0 && w == 0) {
#pragma unroll
                    for (int c2 = 0; c2 < 3; c2++)
                        *(float4*)(bak0 + c2 * 128 + x0) =
                            *(const float4*)(img + c2 * NPIX + y * 128 + x0);
                }
#pragma unroll
                for (int o = 0; o < 3; o++)
                    *(float4*)(img + o * NPIX + y * 128 + x0) =
                        make_float4(res[o][0], res[o][1], res[o][2], res[o][3]);
                __syncthreads();
            }
        } else {
            // ---- last layer: read SMEM, write straight to GMEM ----
            float* ob = out_h + (size_t)b * CPIX;
#pragma unroll 1
            for (int it = 0; it < 8; ++it) {
                const int y = (it << 4) + w;
                const float* rp[3];
                rp[0] = img + ((y + 127) & 127) * 128;
                rp[1] = img + y * 128;
                rp[2] = img + ((y + 1) & 127) * 128;

                float acc[3][4];
#pragma unroll
                for (int o = 0; o < 3; o++)
#pragma unroll
                    for (int p = 0; p < 4; p++) acc[o][p] = cadd[o];

#pragma unroll
                for (int i = 0; i < 3; i++)
#pragma unroll
                    for (int a = 0; a < 3; a++) {
                        const float* r = rp[a] + i * NPIX;
                        const float4 vm = *(const float4*)(r + x0);
                        const float v0 = __shfl_sync(0xffffffffu, vm.w, lm1);
                        const float v5 = __shfl_sync(0xffffffffu, vm.x, lp1);
                        const float v[6] = {v0, vm.x, vm.y, vm.z, vm.w, v5};
#pragma unroll
                        for (int o = 0; o < 3; o++)
#pragma unroll
                            for (int p = 0; p < 4; p++)
#pragma unroll
                                for (int d = 0; d < 3; d++)
                                    acc[o][p] = fmaf(W[o][i][a][d], v[p + d], acc[o][p]);
                    }

#pragma unroll
                for (int o = 0; o < 3; o++) {
                    const int gi = o * NPIX + y * 128 + x0;
                    const float4 c4 = *(const float4*)(clsl + gi);
                    const float4 b4 = *(const float4*)(cbl + gi);
                    const float cp[4] = {c4.x, c4.y, c4.z, c4.w};
                    const float bp[4] = {b4.x, b4.y, b4.z, b4.w};
                    float rr[4];
#pragma unroll
                    for (int p = 0; p < 4; p++) {
                        const float e = __expf(cp[p]);
                        const float v = fmaf(e, acc[o][p], bp[p]);
                        const float t = __logf(fmaf(alpha[o], fabsf(v), 1.0f));
                        ldacc -= t;
                        rr[p] = copysignf(t * inva[o], v);
                    }
                    *(float4*)(ob + gi) = make_float4(rr[0], rr[1], rr[2], rr[3]);
                }
            }
        }
    }

    // ---- per-batch logdet reduction ----
    red[tid] = ldacc;
    __syncthreads();
#pragma unroll
    for (int s2 = 256; s2 > 0; s2 >>= 1) {
        if (tid < s2) red[tid] += red[tid + s2];
        __syncthreads();
    }
    if (tid == 0) {
        float cst = 0.f;
#pragma unroll
        for (int i = 0; i < CONST_BLOCKS; i++) cst += g_partial[i];
        out_ld[b] = red[0] + cst;
    }
}

// ---------------------------------------------------------------------------
extern "C" void kernel_launch(void* const* d_in, const int* in_sizes, int n_in,
                              void* d_out, int out_size)
{
    const float* x    = (const float*)d_in[0];
    const float* anb  = (const float*)d_in[1];
    const float* anls = (const float*)d_in[2];
    const float* K    = (const float*)d_in[3];
    const float* cb   = (const float*)d_in[4];
    const float* cls  = (const float*)d_in[5];
    const float* slal = (const float*)d_in[6];

    const int B = in_sizes[0] / CPIX;           // 512
    float* out_h  = (float*)d_out;
    float* out_ld = (float*)d_out + (out_size - B);

    flow_const_kernel<<<CONST_BLOCKS, 256>>>(anls, K, cls);

    static int smem_set = 0;
    if (!smem_set) {
        cudaFuncSetAttribute(flow_main_kernel,
                             cudaFuncAttributeMaxDynamicSharedMemorySize,
                             SMEM_BYTES);
        smem_set = 1;
    }
    flow_main_kernel<<<B, THREADS, SMEM_BYTES>>>(x, anb, anls, K, cb, cls, slal,
                                                 out_h, out_ld);
}

// round 5
// speedup vs baseline: 1.4792x; 1.0915x over previous
#include <cuda_runtime.h>
#include <cstdint>
#include <math.h>

// Problem constants: B=512, C=3, N=128, k=3, L=3
#define CC 3
#define NN 128
#define NPIX (NN*NN)          // 16384
#define CPIX (CC*NPIX)        // 49152
#define LL 3

#define CONST_BLOCKS (LL * 16)      // 48
__device__ float g_partial[CONST_BLOCKS];
// folded per-layer constants: [0..107] W groups (i*3+a)*12 + o*4 + d,
// [108..110] cadd, [112..114] alpha, [116..118] inva
__device__ float g_fold[LL][128];

// ---------------------------------------------------------------------------
// Prologue: data-independent logdet + actnorm-folded weights.
// grid = 48 blocks (3 layers x 16 freq-chunks), 256 threads.
// ---------------------------------------------------------------------------
__global__ void flow_const_kernel(const float* __restrict__ anls,
                                  const float* __restrict__ anb,
                                  const float* __restrict__ slal,
                                  const float* __restrict__ Kall,
                                  const float* __restrict__ cls)
{
    const int layer = blockIdx.x >> 4;
    const int chunk = blockIdx.x & 15;
    const int tid   = threadIdx.x;
    __shared__ float red[256];

    float kreg[81];
    const float* Kl = Kall + layer * 81;
#pragma unroll
    for (int i = 0; i < 81; i++) kreg[i] = Kl[i];

    // fold actnorm into conv weights (chunk-0 block, 3 threads: one per o)
    if (chunk == 0 && tid < 3) {
        const int o = tid;
        float s[3], bb[3];
#pragma unroll
        for (int i = 0; i < 3; i++) {
            s[i]  = expf(anls[layer * 3 + i]);
            bb[i] = anb[layer * 3 + i];
        }
        float ca = 0.f;
#pragma unroll
        for (int i = 0; i < 3; i++) {
            float ks = 0.f;
#pragma unroll
            for (int a = 0; a < 3; a++)
#pragma unroll
                for (int d = 0; d < 3; d++) {
                    const float kw = kreg[((o * 3 + i) * 3 + a) * 3 + d];
                    g_fold[layer][(i * 3 + a) * 12 + o * 4 + d] = kw * s[i];
                    ks += kw;
                }
            ca = fmaf(ks, bb[i], ca);
        }
        g_fold[layer][108 + o] = ca;
        const float al = expf(slal[layer * 3 + o]);
        g_fold[layer][112 + o] = al;
        g_fold[layer][116 + o] = 1.0f / al;
        // zero the pad lanes once
        if (o == 0) {
            g_fold[layer][111] = 0.f; g_fold[layer][115] = 0.f;
            g_fold[layer][119] = 0.f;
#pragma unroll
            for (int i = 0; i < 9; i++) g_fold[layer][i * 12 + 3]  = 0.f;
#pragma unroll
            for (int i = 0; i < 9; i++) g_fold[layer][i * 12 + 7]  = 0.f;
#pragma unroll
            for (int i = 0; i < 9; i++) g_fold[layer][i * 12 + 11] = 0.f;
        }
    }

    float acc = 0.f;

    // spectral log|det| over this chunk's 1024 frequencies
    for (int ff = tid; ff < 1024; ff += 256) {
        const int f = chunk * 1024 + ff;
        const int u = f >> 7;
        const int v = f & 127;
        float mre[3][3], mim[3][3];
#pragma unroll
        for (int o = 0; o < 3; o++)
#pragma unroll
            for (int i2 = 0; i2 < 3; i2++) { mre[o][i2] = 0.f; mim[o][i2] = 0.f; }

#pragma unroll
        for (int a = 0; a < 3; a++) {
#pragma unroll
            for (int b2 = 0; b2 < 3; b2++) {
                const int m = (u * a + v * b2) & 127;
                float sp, cp;
                sincospif((float)m * (1.0f / 64.0f), &sp, &cp);
#pragma unroll
                for (int o = 0; o < 3; o++)
#pragma unroll
                    for (int i2 = 0; i2 < 3; i2++) {
                        const float kw = kreg[((o * 3 + i2) * 3 + a) * 3 + b2];
                        mre[o][i2] = fmaf(kw, cp, mre[o][i2]);
                        mim[o][i2] = fmaf(-kw, sp, mim[o][i2]);
                    }
            }
        }
        float c0r = mre[1][1] * mre[2][2] - mim[1][1] * mim[2][2]
                  - (mre[1][2] * mre[2][1] - mim[1][2] * mim[2][1]);
        float c0i = mre[1][1] * mim[2][2] + mim[1][1] * mre[2][2]
                  - (mre[1][2] * mim[2][1] + mim[1][2] * mre[2][1]);
        float c1r = mre[1][0] * mre[2][2] - mim[1][0] * mim[2][2]
                  - (mre[1][2] * mre[2][0] - mim[1][2] * mim[2][0]);
        float c1i = mre[1][0] * mim[2][2] + mim[1][0] * mre[2][2]
                  - (mre[1][2] * mim[2][0] + mim[1][2] * mre[2][0]);
        float c2r = mre[1][0] * mre[2][1] - mim[1][0] * mim[2][1]
                  - (mre[1][1] * mre[2][0] - mim[1][1] * mim[2][0]);
        float c2i = mre[1][0] * mim[2][1] + mim[1][0] * mre[2][1]
                  - (mre[1][1] * mim[2][0] + mim[1][1] * mre[2][0]);
        float dr = (mre[0][0] * c0r - mim[0][0] * c0i)
                 - (mre[0][1] * c1r - mim[0][1] * c1i)
                 + (mre[0][2] * c2r - mim[0][2] * c2i);
        float di = (mre[0][0] * c0i + mim[0][0] * c0r)
                 - (mre[0][1] * c1i + mim[0][1] * c1r)
                 + (mre[0][2] * c2i + mim[0][2] * c2r);
        acc += 0.5f * logf(dr * dr + di * di);
    }

    // distributed sum(conv_log_scale[layer])
    const float* cl = cls + layer * CPIX + chunk * (CPIX / 16);
    for (int i = tid; i < CPIX / 16; i += 256) acc += cl[i];

    if (chunk == 0 && tid == 0) {
        float s = anls[layer * 3 + 0] + anls[layer * 3 + 1] + anls[layer * 3 + 2];
        acc += (float)NPIX * s;
    }

    red[tid] = acc;
    __syncthreads();
#pragma unroll
    for (int s2 = 128; s2 > 0; s2 >>= 1) {
        if (tid < s2) red[tid] += red[tid + s2];
        __syncthreads();
    }
    if (tid == 0) g_partial[blockIdx.x] = red[0];
}

// ---------------------------------------------------------------------------
// Main fused kernel: 1 CTA per image, whole image in SMEM, 3 layers fused.
// 1024 threads (32 warps, 64 regs/thread): weights in SMEM via broadcast LDS.
// Each warp processes one full row per chunk; 4 chunks of 32 rows per layer.
// Each lane owns 4 consecutive pixels (float4 LDS + shfl halos).
// ---------------------------------------------------------------------------
#define THREADS 1024
// img + bakP + bak0 + Wsm(3*128) + red(1024)
#define SMEM_FLOATS (CPIX + 384 + 384 + 384 + THREADS)
#define SMEM_BYTES  (SMEM_FLOATS * 4)

__global__ __launch_bounds__(THREADS, 1)
void flow_main_kernel(const float* __restrict__ x,
                      const float* __restrict__ cbias,
                      const float* __restrict__ cls,
                      float* __restrict__ out_h,
                      float* __restrict__ out_ld)
{
    extern __shared__ float sm[];
    float* img  = sm;                 // [3][128][128]
    float* bakP = sm + CPIX;          // [3][128] pre-image of chunk boundary row
    float* bak0 = sm + CPIX + 384;    // [3][128] pre-image of row 0
    float* Wsm  = sm + CPIX + 768;    // [3][128] folded constants
    float* red  = sm + CPIX + 1152;   // [1024]

    const int b   = blockIdx.x;
    const int tid = threadIdx.x;
    const int w   = tid >> 5;         // warp id = row within 32-row chunk
    const int l   = tid & 31;
    const int x0  = l << 2;
    const int lm1 = (l + 31) & 31;
    const int lp1 = (l + 1) & 31;

    // load image (float4 coalesced) + folded constants
    {
        const float4* x4 = (const float4*)(x + (size_t)b * CPIX);
        float4* s4 = (float4*)img;
#pragma unroll
        for (int i = 0; i < CPIX / 4 / THREADS; i++)
            s4[tid + i * THREADS] = x4[tid + i * THREADS];
        if (tid < 384) Wsm[tid] = ((const float*)g_fold)[tid];
    }
    __syncthreads();

    float ldacc = 0.f;

#pragma unroll 1
    for (int layer = 0; layer < LL; ++layer) {
        const float* wl = Wsm + layer * 128;
        const float cadd0 = wl[108], cadd1 = wl[109], cadd2 = wl[110];
        const float al0 = wl[112], al1 = wl[113], al2 = wl[114];
        const float ia0 = wl[116], ia1 = wl[117], ia2 = wl[118];
        const float alpha[3] = {al0, al1, al2};
        const float inva[3]  = {ia0, ia1, ia2};
        const float* clsl = cls   + layer * CPIX;
        const float* cbl  = cbias + layer * CPIX;

        if (layer < LL - 1) {
            // ---- in-place layer: 4 chunks of 32 rows (1 row per warp) ----
#pragma unroll 1
            for (int k = 0; k < 4; k++) {
                const int y = (k << 5) + w;

                const float* rp[3];
                int cs[3];
                if (w == 0) {
                    if (k == 0) { rp[0] = img + 127 * 128; cs[0] = NPIX; }
                    else        { rp[0] = bakP;            cs[0] = 128; }
                } else          { rp[0] = img + (y - 1) * 128; cs[0] = NPIX; }
                rp[1] = img + y * 128; cs[1] = NPIX;
                if (w == 31 && k == 3) { rp[2] = bak0; cs[2] = 128; }
                else                   { rp[2] = img + (y + 1) * 128; cs[2] = NPIX; }

                float acc[3][4];
#pragma unroll
                for (int p = 0; p < 4; p++) {
                    acc[0][p] = cadd0; acc[1][p] = cadd1; acc[2][p] = cadd2;
                }

#pragma unroll
                for (int i = 0; i < 3; i++)
#pragma unroll
                    for (int a = 0; a < 3; a++) {
                        const float* r = rp[a] + i * cs[a];
                        const float4 vm = *(const float4*)(r + x0);
                        const float v0 = __shfl_sync(0xffffffffu, vm.w, lm1);
                        const float v5 = __shfl_sync(0xffffffffu, vm.x, lp1);
                        const float v[6] = {v0, vm.x, vm.y, vm.z, vm.w, v5};
                        const float4* wg4 = (const float4*)(wl + (i * 3 + a) * 12);
#pragma unroll
                        for (int o = 0; o < 3; o++) {
                            const float4 wq = wg4[o];
#pragma unroll
                            for (int p = 0; p < 4; p++) {
                                acc[o][p] = fmaf(wq.x, v[p + 0], acc[o][p]);
                                acc[o][p] = fmaf(wq.y, v[p + 1], acc[o][p]);
                                acc[o][p] = fmaf(wq.z, v[p + 2], acc[o][p]);
                            }
                        }
                    }

                // epilogue: per-pixel scale/bias + slog gate
                float res[3][4];
#pragma unroll
                for (int o = 0; o < 3; o++) {
                    const int gi = o * NPIX + y * 128 + x0;
                    const float4 c4 = *(const float4*)(clsl + gi);
                    const float4 b4 = *(const float4*)(cbl + gi);
                    const float cp[4] = {c4.x, c4.y, c4.z, c4.w};
                    const float bp[4] = {b4.x, b4.y, b4.z, b4.w};
#pragma unroll
                    for (int p = 0; p < 4; p++) {
                        const float e = __expf(cp[p]);
                        const float v = fmaf(e, acc[o][p], bp[p]);
                        const float t = __logf(fmaf(alpha[o], fabsf(v), 1.0f));
                        ldacc -= t;
                        res[o][p] = copysignf(t * inva[o], v);
                    }
                }
                __syncthreads();
                // save halo rows (pre-image), then overwrite (same-thread order)
                if (w == 31) {
#pragma unroll
                    for (int c2 = 0; c2 < 3; c2++)
                        *(float4*)(bakP + c2 * 128 + x0) =
                            *(const float4*)(img + c2 * NPIX + y * 128 + x0);
                }
                if (k == 0 && w == 0) {
#pragma unroll
                    for (int c2 = 0; c2 < 3; c2++)
                        *(float4*)(bak0 + c2 * 128 + x0) =
                            *(const float4*)(img + c2 * NPIX + y * 128 + x0);
                }
#pragma unroll
                for (int o = 0; o < 3; o++)
                    *(float4*)(img + o * NPIX + y * 128 + x0) =
                        make_float4(res[o][0], res[o][1], res[o][2], res[o][3]);
                __syncthreads();
            }
        } else {
            // ---- last layer: read SMEM, write straight to GMEM ----
            float* ob = out_h + (size_t)b * CPIX;
#pragma unroll 1
            for (int it = 0; it < 4; ++it) {
                const int y = (it << 5) + w;
                const float* rp[3];
                rp[0] = img + ((y + 127) & 127) * 128;
                rp[1] = img + y * 128;
                rp[2] = img + ((y + 1) & 127) * 128;

                float acc[3][4];
#pragma unroll
                for (int p = 0; p < 4; p++) {
                    acc[0][p] = cadd0; acc[1][p] = cadd1; acc[2][p] = cadd2;
                }

#pragma unroll
                for (int i = 0; i < 3; i++)
#pragma unroll
                    for (int a = 0; a < 3; a++) {
                        const float* r = rp[a] + i * NPIX;
                        const float4 vm = *(const float4*)(r + x0);
                        const float v0 = __shfl_sync(0xffffffffu, vm.w, lm1);
                        const float v5 = __shfl_sync(0xffffffffu, vm.x, lp1);
                        const float v[6] = {v0, vm.x, vm.y, vm.z, vm.w, v5};
                        const float4* wg4 = (const float4*)(wl + (i * 3 + a) * 12);
#pragma unroll
                        for (int o = 0; o < 3; o++) {
                            const float4 wq = wg4[o];
#pragma unroll
                            for (int p = 0; p < 4; p++) {
                                acc[o][p] = fmaf(wq.x, v[p + 0], acc[o][p]);
                                acc[o][p] = fmaf(wq.y, v[p + 1], acc[o][p]);
                                acc[o][p] = fmaf(wq.z, v[p + 2], acc[o][p]);
                            }
                        }
                    }

#pragma unroll
                for (int o = 0; o < 3; o++) {
                    const int gi = o * NPIX + y * 128 + x0;
                    const float4 c4 = *(const float4*)(clsl + gi);
                    const float4 b4 = *(const float4*)(cbl + gi);
                    const float cp[4] = {c4.x, c4.y, c4.z, c4.w};
                    const float bp[4] = {b4.x, b4.y, b4.z, b4.w};
                    float rr[4];
#pragma unroll
                    for (int p = 0; p < 4; p++) {
                        const float e = __expf(cp[p]);
                        const float v = fmaf(e, acc[o][p], bp[p]);
                        const float t = __logf(fmaf(alpha[o], fabsf(v), 1.0f));
                        ldacc -= t;
                        rr[p] = copysignf(t * inva[o], v);
                    }
                    *(float4*)(ob + gi) = make_float4(rr[0], rr[1], rr[2], rr[3]);
                }
            }
        }
    }

    // ---- per-batch logdet reduction ----
    red[tid] = ldacc;
    __syncthreads();
#pragma unroll
    for (int s2 = 512; s2 > 0; s2 >>= 1) {
        if (tid < s2) red[tid] += red[tid + s2];
        __syncthreads();
    }
    if (tid == 0) {
        float cst = 0.f;
#pragma unroll
        for (int i = 0; i < CONST_BLOCKS; i++) cst += g_partial[i];
        out_ld[b] = red[0] + cst;
    }
}

// ---------------------------------------------------------------------------
extern "C" void kernel_launch(void* const* d_in, const int* in_sizes, int n_in,
                              void* d_out, int out_size)
{
    const float* x    = (const float*)d_in[0];
    const float* anb  = (const float*)d_in[1];
    const float* anls = (const float*)d_in[2];
    const float* K    = (const float*)d_in[3];
    const float* cb   = (const float*)d_in[4];
    const float* cls  = (const float*)d_in[5];
    const float* slal = (const float*)d_in[6];

    const int B = in_sizes[0] / CPIX;           // 512
    float* out_h  = (float*)d_out;
    float* out_ld = (float*)d_out + (out_size - B);

    flow_const_kernel<<<CONST_BLOCKS, 256>>>(anls, anb, slal, K, cls);

    static int smem_set = 0;
    if (!smem_set) {
        cudaFuncSetAttribute(flow_main_kernel,
                             cudaFuncAttributeMaxDynamicSharedMemorySize,
                             SMEM_BYTES);
        smem_set = 1;
    }
    flow_main_kernel<<<B, THREADS, SMEM_BYTES>>>(x, cb, cls, out_h, out_ld);
}